// round 16
// baseline (speedup 1.0000x reference)
#include <cuda_runtime.h>
#include <cuda_bf16.h>
#include <math.h>
#include <stdint.h>

// ---------------- problem constants ----------------
#define B_   64
#define T_   512
#define D_   256
#define FF_  512
#define L_   4
#define H_   8
#define HD_  32
#define M_   (B_*T_)          // 32768 rows

// ---------------- scratch (device globals; no allocation allowed) ----------------
__device__ float g_x   [M_*D_];
__device__ float g_ln  [M_*D_];
__device__ float g_qkv [M_*3*D_];
__device__ float g_attn[M_*D_];
__device__ float g_h1  [M_*FF_];
__device__ int   g_mask_u8;

// ---------------- mask dtype detection ----------------
__global__ void detect_mask_kernel(const unsigned char* __restrict__ m)
{
    __shared__ int s_any;
    if (threadIdx.x == 0) s_any = 0;
    __syncthreads();
    int any = 0;
    for (int i = threadIdx.x; i < M_; i += 256)
        if ((i & 3) && m[i]) any = 1;
    if (any) atomicOr(&s_any, 1);
    __syncthreads();
    if (threadIdx.x == 0) g_mask_u8 = s_any;
}

// ---------------- embedding ----------------
__global__ void embed_kernel(const float* __restrict__ latents,
                             const int*   __restrict__ move_ids,
                             const float* __restrict__ pos,
                             const float* __restrict__ efrom,
                             const float* __restrict__ eto,
                             const float* __restrict__ epromo)
{
    int row = blockIdx.x;
    int d   = threadIdx.x;
    int t   = row & (T_-1);
    int mid = move_ids[row];
    int promo = mid >> 12;
    int rem   = mid & 4095;
    int frm   = rem >> 6;
    int to    = rem & 63;
    size_t off = (size_t)row * D_ + d;
    g_x[off] = latents[off] + pos[t*D_ + d] + efrom[frm*D_ + d]
             + eto[to*D_ + d] + epromo[promo*D_ + d];
}

// ---------------- warp-level sum ----------------
__device__ __forceinline__ float warpSum(float v)
{
    #pragma unroll
    for (int off = 16; off; off >>= 1) v += __shfl_xor_sync(0xffffffffu, v, off);
    return v;
}

// ---------------- layernorm: one warp per row, 8 rows per CTA ----------------
__global__ void ln_kernel(const float* __restrict__ x,
                          const float* __restrict__ w,
                          const float* __restrict__ b,
                          float* __restrict__ y)
{
    int row  = blockIdx.x * 8 + (threadIdx.x >> 5);
    int lane = threadIdx.x & 31;
    const float4* xr = (const float4*)(x + (size_t)row * D_);
    float4 v0 = xr[lane], v1 = xr[lane + 32];
    float s = v0.x+v0.y+v0.z+v0.w + v1.x+v1.y+v1.z+v1.w;
    float mean = warpSum(s) * (1.f/(float)D_);
    float d0x=v0.x-mean, d0y=v0.y-mean, d0z=v0.z-mean, d0w=v0.w-mean;
    float d1x=v1.x-mean, d1y=v1.y-mean, d1z=v1.z-mean, d1w=v1.w-mean;
    float q = d0x*d0x+d0y*d0y+d0z*d0z+d0w*d0w
            + d1x*d1x+d1y*d1y+d1z*d1z+d1w*d1w;
    float var = warpSum(q) * (1.f/(float)D_);
    float r = rsqrtf(var + 1e-5f);
    float4 w0 = ((const float4*)w)[lane], w1 = ((const float4*)w)[lane+32];
    float4 b0 = ((const float4*)b)[lane], b1 = ((const float4*)b)[lane+32];
    float4* yr = (float4*)(y + (size_t)row * D_);
    yr[lane]      = make_float4(fmaf(d0x*r, w0.x, b0.x), fmaf(d0y*r, w0.y, b0.y),
                                fmaf(d0z*r, w0.z, b0.z), fmaf(d0w*r, w0.w, b0.w));
    yr[lane + 32] = make_float4(fmaf(d1x*r, w1.x, b1.x), fmaf(d1y*r, w1.y, b1.y),
                                fmaf(d1z*r, w1.z, b1.z), fmaf(d1w*r, w1.w, b1.w));
}

__global__ void ln_mask_kernel(const float* __restrict__ x,
                               const float* __restrict__ w,
                               const float* __restrict__ b,
                               const unsigned char* __restrict__ mask_u8,
                               const int*           __restrict__ mask_i32,
                               const float* __restrict__ latents,
                               float* __restrict__ out)
{
    int row  = blockIdx.x * 8 + (threadIdx.x >> 5);
    int lane = threadIdx.x & 31;
    const float4* xr = (const float4*)(x + (size_t)row * D_);
    float4 v0 = xr[lane], v1 = xr[lane + 32];
    float s = v0.x+v0.y+v0.z+v0.w + v1.x+v1.y+v1.z+v1.w;
    float mean = warpSum(s) * (1.f/(float)D_);
    float d0x=v0.x-mean, d0y=v0.y-mean, d0z=v0.z-mean, d0w=v0.w-mean;
    float d1x=v1.x-mean, d1y=v1.y-mean, d1z=v1.z-mean, d1w=v1.w-mean;
    float q = d0x*d0x+d0y*d0y+d0z*d0z+d0w*d0w
            + d1x*d1x+d1y*d1y+d1z*d1z+d1w*d1w;
    float var = warpSum(q) * (1.f/(float)D_);
    float r = rsqrtf(var + 1e-5f);
    float4 w0 = ((const float4*)w)[lane], w1 = ((const float4*)w)[lane+32];
    float4 b0 = ((const float4*)b)[lane], b1 = ((const float4*)b)[lane+32];
    int m = g_mask_u8 ? (int)mask_u8[row] : mask_i32[row];
    const float4* lr = (const float4*)(latents + (size_t)row * D_);
    float4* yr = (float4*)(out + (size_t)row * D_);
    if (m) {
        yr[lane]      = make_float4(fmaf(d0x*r, w0.x, b0.x), fmaf(d0y*r, w0.y, b0.y),
                                    fmaf(d0z*r, w0.z, b0.z), fmaf(d0w*r, w0.w, b0.w));
        yr[lane + 32] = make_float4(fmaf(d1x*r, w1.x, b1.x), fmaf(d1y*r, w1.y, b1.y),
                                    fmaf(d1z*r, w1.z, b1.z), fmaf(d1w*r, w1.w, b1.w));
    } else {
        yr[lane]      = lr[lane];
        yr[lane + 32] = lr[lane + 32];
    }
}

// ---------------- mma / cp.async / ldmatrix helpers ----------------
__device__ __forceinline__ void mma_tf32(float* d, const uint32_t* a, const uint32_t* b)
{
    asm volatile(
        "mma.sync.aligned.m16n8k8.row.col.f32.tf32.tf32.f32 "
        "{%0,%1,%2,%3},{%4,%5,%6,%7},{%8,%9},{%0,%1,%2,%3};"
        : "+f"(d[0]), "+f"(d[1]), "+f"(d[2]), "+f"(d[3])
        : "r"(a[0]), "r"(a[1]), "r"(a[2]), "r"(a[3]), "r"(b[0]), "r"(b[1]));
}

__device__ __forceinline__ void ldsm_x4(uint32_t* r, const float* p)
{
    uint32_t a = (uint32_t)__cvta_generic_to_shared(p);
    asm volatile("ldmatrix.sync.aligned.m8n8.x4.shared.b16 {%0,%1,%2,%3}, [%4];"
                 : "=r"(r[0]), "=r"(r[1]), "=r"(r[2]), "=r"(r[3]) : "r"(a));
}

__device__ __forceinline__ void cp_async16(void* smem_dst, const void* gsrc)
{
    uint32_t sa = (uint32_t)__cvta_generic_to_shared(smem_dst);
    asm volatile("cp.async.ca.shared.global [%0], [%1], 16;" :: "r"(sa), "l"(gsrc));
}
#define CP_COMMIT() asm volatile("cp.async.commit_group;")

// software exp: FMA pipe only (no MUFU)
__device__ __forceinline__ float fast_exp(float x)
{
    x = fmaxf(x, -80.f);
    float y = x * 1.4426950408889634f;
    float r = rintf(y);
    float f = y - r;
    float z = 1.3333558146e-3f;
    z = fmaf(z, f, 9.6181291076e-3f);
    z = fmaf(z, f, 5.5504108664e-2f);
    z = fmaf(z, f, 2.4022650696e-1f);
    z = fmaf(z, f, 6.9314718056e-1f);
    z = fmaf(z, f, 1.0f);
    float sc = __int_as_float(((int)r + 127) << 23);
    return z * sc;
}

// ---------------- double-buffered tf32 GEMM: BM=128, BN=128, warp tile 64x32 ----
#define GSTR 36
#define ASZ (128 * GSTR)
#define BSZ (128 * GSTR)
#define GEMM_SMEM ((2*ASZ + 2*BSZ) * 4)

template<bool RESID, bool RELU>
__global__ void __launch_bounds__(256)
gemm_db_kernel(const float* __restrict__ A,
               const float* __restrict__ W,
               const float* __restrict__ bias,
               float* __restrict__ C,
               int M, int N, int K)
{
    extern __shared__ float smem[];
    float* Abuf = smem;
    float* Bbuf = smem + 2*ASZ;

    int tid  = threadIdx.x;
    int warp = tid >> 5, lane = tid & 31;
    int g  = lane >> 2, tg = lane & 3;
    int lr = lane & 7, sel = lane >> 3;
    int wm = (warp >> 2) * 64;          // 2 warp-rows
    int wn = (warp & 3)  * 32;          // 4 warp-cols
    int bm = blockIdx.y * 128, bn = blockIdx.x * 128;

    // ldmatrix per-lane row/col offsets
    int a_r = ((sel & 1) << 3) + lr;    // A: rows 0-7 / 8-15 per 16-block
    int a_c = (sel >> 1) << 2;          //    col quads 0-3 / 4-7
    int b_r = ((sel >> 1) << 3) + lr;   // B: nj rows
    int b_c = (sel & 1) << 2;

    auto load_tiles = [&](int k0, int buf) {
        float* As = Abuf + buf * ASZ;
        float* Bs = Bbuf + buf * BSZ;
        #pragma unroll
        for (int it = 0; it < 4; ++it) {
            int idx = tid + it * 256;          // 1024 float4 slots
            int r = idx >> 3, c4 = (idx & 7) << 2;
            cp_async16(&As[r * GSTR + c4], A + (size_t)(bm + r) * K + k0 + c4);
        }
        #pragma unroll
        for (int it = 0; it < 4; ++it) {
            int idx = tid + it * 256;
            int r = idx >> 3, c4 = (idx & 7) << 2;
            cp_async16(&Bs[r * GSTR + c4], W + (size_t)(bn + r) * K + k0 + c4);
        }
    };

    float acc[4][4][4] = {};
    int niter = K >> 5;

    load_tiles(0, 0);
    CP_COMMIT();

    for (int it = 0; it < niter; ++it) {
        if (it + 1 < niter) {
            load_tiles((it + 1) << 5, (it + 1) & 1);
            CP_COMMIT();
            asm volatile("cp.async.wait_group 1;");
        } else {
            asm volatile("cp.async.wait_group 0;");
        }
        __syncthreads();

        float* As = Abuf + (it & 1) * ASZ;
        float* Bs = Bbuf + (it & 1) * BSZ;
        #pragma unroll
        for (int ks = 0; ks < 4; ++ks) {
            int kk = ks * 8;
            uint32_t a[4][4], b[2][4];
            #pragma unroll
            for (int mi = 0; mi < 4; ++mi)
                ldsm_x4(a[mi], &As[(wm + mi*16 + a_r) * GSTR + kk + a_c]);
            ldsm_x4(b[0], &Bs[(wn +      b_r) * GSTR + kk + b_c]);
            ldsm_x4(b[1], &Bs[(wn + 16 + b_r) * GSTR + kk + b_c]);
            #pragma unroll
            for (int mi = 0; mi < 4; ++mi)
                #pragma unroll
                for (int nj = 0; nj < 4; ++nj)
                    mma_tf32(acc[mi][nj], a[mi], &b[nj >> 1][(nj & 1) << 1]);
        }
        __syncthreads();
    }

    #pragma unroll
    for (int mi = 0; mi < 4; ++mi) {
        #pragma unroll
        for (int nj = 0; nj < 4; ++nj) {
            int r0 = bm + wm + mi * 16 + g;
            int c0 = bn + wn + nj * 8 + 2 * tg;
            float bv0 = bias[c0], bv1 = bias[c0 + 1];
            float v00 = acc[mi][nj][0] + bv0;
            float v01 = acc[mi][nj][1] + bv1;
            float v10 = acc[mi][nj][2] + bv0;
            float v11 = acc[mi][nj][3] + bv1;
            if (RELU) {
                v00 = fmaxf(v00, 0.f); v01 = fmaxf(v01, 0.f);
                v10 = fmaxf(v10, 0.f); v11 = fmaxf(v11, 0.f);
            }
            float2* p0 = (float2*)(C + (size_t)r0 * N + c0);
            float2* p1 = (float2*)(C + (size_t)(r0 + 8) * N + c0);
            if (RESID) {
                float2 o0 = *p0, o1 = *p1;
                v00 += o0.x; v01 += o0.y; v10 += o1.x; v11 += o1.y;
            }
            *p0 = make_float2(v00, v01);
            *p1 = make_float2(v10, v11);
        }
    }
}

// ---------------- tensor-core flash attention with ldmatrix ----------------
#define AKS 36
#define VSTR 516
#define APS 68
#define ATTN_SMEM ((T_*AKS + HD_*VSTR + 16*16*APS) * 4)

__global__ void attn_tc_kernel(const float* __restrict__ qkv,
                               float* __restrict__ attn_out)
{
    extern __shared__ float sm[];
    float* Ksh = sm;
    float* Vt  = Ksh + T_*AKS;
    float* Psh = Vt + HD_*VSTR;

    int bh = blockIdx.x, b = bh >> 3, h = bh & 7;
    int tid = threadIdx.x;
    int warp = tid >> 5, lane = tid & 31;
    int g = lane >> 2, tg = lane & 3;
    int lr = lane & 7, sel = lane >> 3;

    const float* base = qkv + (size_t)b * T_ * 768 + h * HD_;
    for (int idx = tid; idx < T_*HD_; idx += 512) {
        int j = idx >> 5, d = idx & 31;
        Ksh[j*AKS + d]  = base[(size_t)j*768 + 256 + d];
        Vt [d*VSTR + j] = base[(size_t)j*768 + 512 + d];
    }
    __syncthreads();

    float* Pw = Psh + warp * 16 * APS;
    const float scale = 0.17677669529663687f;

    int p_r = ((sel & 1) << 3) + lr;
    int p_c = (sel >> 1) << 2;
    int kv_c = sel << 2;

    #pragma unroll
    for (int s = 0; s < 2; ++s) {
        int qt = s ? (31 - warp) : warp;
        int row0 = qt * 16;

        uint32_t aq[4][4];
        const float* q0 = qkv + (size_t)(b*T_ + row0) * 768 + h * HD_;
        #pragma unroll
        for (int ks = 0; ks < 4; ++ks) {
            int kk = ks * 8;
            aq[ks][0] = __float_as_uint(q0[(size_t)g*768     + kk+tg  ] * scale);
            aq[ks][1] = __float_as_uint(q0[(size_t)(g+8)*768 + kk+tg  ] * scale);
            aq[ks][2] = __float_as_uint(q0[(size_t)g*768     + kk+tg+4] * scale);
            aq[ks][3] = __float_as_uint(q0[(size_t)(g+8)*768 + kk+tg+4] * scale);
        }

        int kend  = row0 + 16;
        int jmax0 = kend - 8;
        float m0 = -1e30f, m1 = -1e30f, l0 = 0.f, l1 = 0.f;
        float acc[4][4] = {};

        for (int jb = 0; jb < kend; jb += 64) {
            int chunk = min(64, kend - jb);
            int nbl = chunk >> 3;

            float sc[8][4];
            #pragma unroll
            for (int nb = 0; nb < 8; ++nb) if (nb < nbl) {
                float c4[4] = {0.f, 0.f, 0.f, 0.f};
                const float* krow = &Ksh[(jb + nb*8 + lr) * AKS];
                uint32_t kf[8];
                ldsm_x4(kf,     krow + kv_c);
                ldsm_x4(kf + 4, krow + 16 + kv_c);
                #pragma unroll
                for (int ks = 0; ks < 4; ++ks)
                    mma_tf32(c4, aq[ks], kf + ks*2);
                sc[nb][0] = c4[0]; sc[nb][1] = c4[1];
                sc[nb][2] = c4[2]; sc[nb][3] = c4[3];
            }

            if (jb + chunk > jmax0) {
                #pragma unroll
                for (int nb = 0; nb < 8; ++nb) if (nb < nbl) {
                    int jj = jb + nb*8 + 2*tg;
                    if (jj     >= jmax0) sc[nb][0] = -1e30f;
                    if (jj + 1 >= jmax0) sc[nb][1] = -1e30f;
                }
            }

            float c0 = -1e30f, c1 = -1e30f;
            #pragma unroll
            for (int nb = 0; nb < 8; ++nb) if (nb < nbl) {
                c0 = fmaxf(c0, fmaxf(sc[nb][0], sc[nb][1]));
                c1 = fmaxf(c1, fmaxf(sc[nb][2], sc[nb][3]));
            }
            c0 = fmaxf(c0, __shfl_xor_sync(0xffffffffu, c0, 1));
            c0 = fmaxf(c0, __shfl_xor_sync(0xffffffffu, c0, 2));
            c1 = fmaxf(c1, __shfl_xor_sync(0xffffffffu, c1, 1));
            c1 = fmaxf(c1, __shfl_xor_sync(0xffffffffu, c1, 2));

            float m0n = fmaxf(m0, c0), m1n = fmaxf(m1, c1);
            float f0 = fast_exp(m0 - m0n), f1 = fast_exp(m1 - m1n);

            float sum0 = 0.f, sum1 = 0.f;
            #pragma unroll
            for (int nb = 0; nb < 8; ++nb) if (nb < nbl) {
                float p00 = fast_exp(sc[nb][0] - m0n);
                float p01 = fast_exp(sc[nb][1] - m0n);
                float p10 = fast_exp(sc[nb][2] - m1n);
                float p11 = fast_exp(sc[nb][3] - m1n);
                sum0 += p00 + p01;
                sum1 += p10 + p11;
                *(float2*)(&Pw[(g    )*APS + nb*8 + 2*tg]) = make_float2(p00, p01);
                *(float2*)(&Pw[(g + 8)*APS + nb*8 + 2*tg]) = make_float2(p10, p11);
            }
            sum0 += __shfl_xor_sync(0xffffffffu, sum0, 1);
            sum0 += __shfl_xor_sync(0xffffffffu, sum0, 2);
            sum1 += __shfl_xor_sync(0xffffffffu, sum1, 1);
            sum1 += __shfl_xor_sync(0xffffffffu, sum1, 2);

            l0 = l0 * f0 + sum0;
            l1 = l1 * f1 + sum1;
            m0 = m0n; m1 = m1n;

            #pragma unroll
            for (int nb2 = 0; nb2 < 4; ++nb2) {
                acc[nb2][0] *= f0; acc[nb2][1] *= f0;
                acc[nb2][2] *= f1; acc[nb2][3] *= f1;
            }
            __syncwarp();

            #pragma unroll
            for (int ksp = 0; ksp < 4; ++ksp) if (ksp < (nbl >> 1)) {
                uint32_t pa[2][4];
                ldsm_x4(pa[0], &Pw[p_r*APS + (2*ksp  )*8 + p_c]);
                ldsm_x4(pa[1], &Pw[p_r*APS + (2*ksp+1)*8 + p_c]);
                #pragma unroll
                for (int nb2 = 0; nb2 < 4; ++nb2) {
                    uint32_t vf[4];
                    ldsm_x4(vf, &Vt[(nb2*8 + lr)*VSTR + jb + ksp*16 + kv_c]);
                    mma_tf32(acc[nb2], pa[0], vf);
                    mma_tf32(acc[nb2], pa[1], vf + 2);
                }
            }
            __syncwarp();
        }

        float inv0 = 1.f / l0, inv1 = 1.f / l1;
        #pragma unroll
        for (int nb2 = 0; nb2 < 4; ++nb2) {
            int d = nb2*8 + 2*tg;
            float* o0 = attn_out + (size_t)(b*T_ + row0 + g    ) * D_ + h*HD_ + d;
            float* o1 = attn_out + (size_t)(b*T_ + row0 + g + 8) * D_ + h*HD_ + d;
            *(float2*)o0 = make_float2(acc[nb2][0]*inv0, acc[nb2][1]*inv0);
            *(float2*)o1 = make_float2(acc[nb2][2]*inv1, acc[nb2][3]*inv1);
        }
    }
}

// ---------------- launch ----------------
extern "C" void kernel_launch(void* const* d_in, const int* in_sizes, int n_in,
                              void* d_out, int out_size)
{
    const float*         latents  = (const float*)d_in[0];
    const int*           move_ids = (const int*)d_in[1];
    const void*          mask     = d_in[2];
    const float*         pos      = (const float*)d_in[3];
    const float*         efrom    = (const float*)d_in[4];
    const float*         eto      = (const float*)d_in[5];
    const float*         epromo   = (const float*)d_in[6];
    const float*         in_proj_w= (const float*)d_in[7];
    const float*         in_proj_b= (const float*)d_in[8];
    const float*         out_w    = (const float*)d_in[9];
    const float*         out_b    = (const float*)d_in[10];
    const float*         fc1_w    = (const float*)d_in[11];
    const float*         fc1_b    = (const float*)d_in[12];
    const float*         fc2_w    = (const float*)d_in[13];
    const float*         fc2_b    = (const float*)d_in[14];
    const float*         norm_w   = (const float*)d_in[15];
    const float*         norm_b   = (const float*)d_in[16];
    float* out = (float*)d_out;

    float *px, *pln, *pqkv, *pattn, *ph1;
    cudaGetSymbolAddress((void**)&px,    g_x);
    cudaGetSymbolAddress((void**)&pln,   g_ln);
    cudaGetSymbolAddress((void**)&pqkv,  g_qkv);
    cudaGetSymbolAddress((void**)&pattn, g_attn);
    cudaGetSymbolAddress((void**)&ph1,   g_h1);

    cudaFuncSetAttribute(attn_tc_kernel,
                         cudaFuncAttributeMaxDynamicSharedMemorySize, ATTN_SMEM);
    cudaFuncSetAttribute(gemm_db_kernel<false,false>,
                         cudaFuncAttributeMaxDynamicSharedMemorySize, GEMM_SMEM);
    cudaFuncSetAttribute(gemm_db_kernel<true,false>,
                         cudaFuncAttributeMaxDynamicSharedMemorySize, GEMM_SMEM);
    cudaFuncSetAttribute(gemm_db_kernel<false,true>,
                         cudaFuncAttributeMaxDynamicSharedMemorySize, GEMM_SMEM);

    detect_mask_kernel<<<1, 256>>>((const unsigned char*)mask);
    embed_kernel<<<M_, 256>>>(latents, move_ids, pos, efrom, eto, epromo);

    for (int l = 0; l < L_; ++l) {
        ln_kernel<<<M_/8, 256>>>(px, norm_w, norm_b, pln);
        gemm_db_kernel<false,false><<<dim3(3*D_/128, M_/128), 256, GEMM_SMEM>>>(
            pln, in_proj_w + (size_t)l*3*D_*D_, in_proj_b + l*3*D_, pqkv, M_, 3*D_, D_);
        attn_tc_kernel<<<B_*H_, 512, ATTN_SMEM>>>(pqkv, pattn);
        gemm_db_kernel<true,false><<<dim3(D_/128, M_/128), 256, GEMM_SMEM>>>(
            pattn, out_w + (size_t)l*D_*D_, out_b + l*D_, px, M_, D_, D_);
        ln_kernel<<<M_/8, 256>>>(px, norm_w, norm_b, pln);
        gemm_db_kernel<false,true><<<dim3(FF_/128, M_/128), 256, GEMM_SMEM>>>(
            pln, fc1_w + (size_t)l*FF_*D_, fc1_b + l*FF_, ph1, M_, FF_, D_);
        gemm_db_kernel<true,false><<<dim3(D_/128, M_/128), 256, GEMM_SMEM>>>(
            ph1, fc2_w + (size_t)l*D_*FF_, fc2_b + l*D_, px, M_, D_, FF_);
    }

    ln_mask_kernel<<<M_/8, 256>>>(px, norm_w, norm_b,
                                  (const unsigned char*)mask, (const int*)mask,
                                  latents, out);
}

// round 17
// speedup vs baseline: 1.0012x; 1.0012x over previous
#include <cuda_runtime.h>
#include <cuda_bf16.h>
#include <math.h>
#include <stdint.h>

// ---------------- problem constants ----------------
#define B_   64
#define T_   512
#define D_   256
#define FF_  512
#define L_   4
#define H_   8
#define HD_  32
#define M_   (B_*T_)          // 32768 rows

// ---------------- scratch (device globals; no allocation allowed) ----------------
__device__ float g_x   [M_*D_];
__device__ float g_ln  [M_*D_];
__device__ float g_qkv [M_*3*D_];
__device__ float g_attn[M_*D_];
__device__ float g_h1  [M_*FF_];
__device__ int   g_mask_u8;

// ---------------- mask dtype detection ----------------
__global__ void detect_mask_kernel(const unsigned char* __restrict__ m)
{
    __shared__ int s_any;
    if (threadIdx.x == 0) s_any = 0;
    __syncthreads();
    int any = 0;
    for (int i = threadIdx.x; i < M_; i += 256)
        if ((i & 3) && m[i]) any = 1;
    if (any) atomicOr(&s_any, 1);
    __syncthreads();
    if (threadIdx.x == 0) g_mask_u8 = s_any;
}

// ---------------- embedding ----------------
__global__ void embed_kernel(const float* __restrict__ latents,
                             const int*   __restrict__ move_ids,
                             const float* __restrict__ pos,
                             const float* __restrict__ efrom,
                             const float* __restrict__ eto,
                             const float* __restrict__ epromo)
{
    int row = blockIdx.x;
    int d   = threadIdx.x;
    int t   = row & (T_-1);
    int mid = move_ids[row];
    int promo = mid >> 12;
    int rem   = mid & 4095;
    int frm   = rem >> 6;
    int to    = rem & 63;
    size_t off = (size_t)row * D_ + d;
    g_x[off] = latents[off] + pos[t*D_ + d] + efrom[frm*D_ + d]
             + eto[to*D_ + d] + epromo[promo*D_ + d];
}

// ---------------- warp-level sum ----------------
__device__ __forceinline__ float warpSum(float v)
{
    #pragma unroll
    for (int off = 16; off; off >>= 1) v += __shfl_xor_sync(0xffffffffu, v, off);
    return v;
}

// ---------------- layernorm: one warp per row, 8 rows per CTA ----------------
__global__ void ln_kernel(const float* __restrict__ x,
                          const float* __restrict__ w,
                          const float* __restrict__ b,
                          float* __restrict__ y)
{
    int row  = blockIdx.x * 8 + (threadIdx.x >> 5);
    int lane = threadIdx.x & 31;
    const float4* xr = (const float4*)(x + (size_t)row * D_);
    float4 v0 = xr[lane], v1 = xr[lane + 32];
    float s = v0.x+v0.y+v0.z+v0.w + v1.x+v1.y+v1.z+v1.w;
    float mean = warpSum(s) * (1.f/(float)D_);
    float d0x=v0.x-mean, d0y=v0.y-mean, d0z=v0.z-mean, d0w=v0.w-mean;
    float d1x=v1.x-mean, d1y=v1.y-mean, d1z=v1.z-mean, d1w=v1.w-mean;
    float q = d0x*d0x+d0y*d0y+d0z*d0z+d0w*d0w
            + d1x*d1x+d1y*d1y+d1z*d1z+d1w*d1w;
    float var = warpSum(q) * (1.f/(float)D_);
    float r = rsqrtf(var + 1e-5f);
    float4 w0 = ((const float4*)w)[lane], w1 = ((const float4*)w)[lane+32];
    float4 b0 = ((const float4*)b)[lane], b1 = ((const float4*)b)[lane+32];
    float4* yr = (float4*)(y + (size_t)row * D_);
    yr[lane]      = make_float4(fmaf(d0x*r, w0.x, b0.x), fmaf(d0y*r, w0.y, b0.y),
                                fmaf(d0z*r, w0.z, b0.z), fmaf(d0w*r, w0.w, b0.w));
    yr[lane + 32] = make_float4(fmaf(d1x*r, w1.x, b1.x), fmaf(d1y*r, w1.y, b1.y),
                                fmaf(d1z*r, w1.z, b1.z), fmaf(d1w*r, w1.w, b1.w));
}

__global__ void ln_mask_kernel(const float* __restrict__ x,
                               const float* __restrict__ w,
                               const float* __restrict__ b,
                               const unsigned char* __restrict__ mask_u8,
                               const int*           __restrict__ mask_i32,
                               const float* __restrict__ latents,
                               float* __restrict__ out)
{
    int row  = blockIdx.x * 8 + (threadIdx.x >> 5);
    int lane = threadIdx.x & 31;
    const float4* xr = (const float4*)(x + (size_t)row * D_);
    float4 v0 = xr[lane], v1 = xr[lane + 32];
    float s = v0.x+v0.y+v0.z+v0.w + v1.x+v1.y+v1.z+v1.w;
    float mean = warpSum(s) * (1.f/(float)D_);
    float d0x=v0.x-mean, d0y=v0.y-mean, d0z=v0.z-mean, d0w=v0.w-mean;
    float d1x=v1.x-mean, d1y=v1.y-mean, d1z=v1.z-mean, d1w=v1.w-mean;
    float q = d0x*d0x+d0y*d0y+d0z*d0z+d0w*d0w
            + d1x*d1x+d1y*d1y+d1z*d1z+d1w*d1w;
    float var = warpSum(q) * (1.f/(float)D_);
    float r = rsqrtf(var + 1e-5f);
    float4 w0 = ((const float4*)w)[lane], w1 = ((const float4*)w)[lane+32];
    float4 b0 = ((const float4*)b)[lane], b1 = ((const float4*)b)[lane+32];
    int m = g_mask_u8 ? (int)mask_u8[row] : mask_i32[row];
    const float4* lr = (const float4*)(latents + (size_t)row * D_);
    float4* yr = (float4*)(out + (size_t)row * D_);
    if (m) {
        yr[lane]      = make_float4(fmaf(d0x*r, w0.x, b0.x), fmaf(d0y*r, w0.y, b0.y),
                                    fmaf(d0z*r, w0.z, b0.z), fmaf(d0w*r, w0.w, b0.w));
        yr[lane + 32] = make_float4(fmaf(d1x*r, w1.x, b1.x), fmaf(d1y*r, w1.y, b1.y),
                                    fmaf(d1z*r, w1.z, b1.z), fmaf(d1w*r, w1.w, b1.w));
    } else {
        yr[lane]      = lr[lane];
        yr[lane + 32] = lr[lane + 32];
    }
}

// ---------------- mma / cp.async / ldmatrix helpers ----------------
__device__ __forceinline__ void mma_tf32(float* d, const uint32_t* a, const uint32_t* b)
{
    asm volatile(
        "mma.sync.aligned.m16n8k8.row.col.f32.tf32.tf32.f32 "
        "{%0,%1,%2,%3},{%4,%5,%6,%7},{%8,%9},{%0,%1,%2,%3};"
        : "+f"(d[0]), "+f"(d[1]), "+f"(d[2]), "+f"(d[3])
        : "r"(a[0]), "r"(a[1]), "r"(a[2]), "r"(a[3]), "r"(b[0]), "r"(b[1]));
}

__device__ __forceinline__ void ldsm_x4(uint32_t* r, const float* p)
{
    uint32_t a = (uint32_t)__cvta_generic_to_shared(p);
    asm volatile("ldmatrix.sync.aligned.m8n8.x4.shared.b16 {%0,%1,%2,%3}, [%4];"
                 : "=r"(r[0]), "=r"(r[1]), "=r"(r[2]), "=r"(r[3]) : "r"(a));
}

__device__ __forceinline__ void cp_async16(void* smem_dst, const void* gsrc)
{
    uint32_t sa = (uint32_t)__cvta_generic_to_shared(smem_dst);
    asm volatile("cp.async.ca.shared.global [%0], [%1], 16;" :: "r"(sa), "l"(gsrc));
}
#define CP_COMMIT() asm volatile("cp.async.commit_group;")

// software exp: FMA pipe only (no MUFU)
__device__ __forceinline__ float fast_exp(float x)
{
    x = fmaxf(x, -80.f);
    float y = x * 1.4426950408889634f;
    float r = rintf(y);
    float f = y - r;
    float z = 1.3333558146e-3f;
    z = fmaf(z, f, 9.6181291076e-3f);
    z = fmaf(z, f, 5.5504108664e-2f);
    z = fmaf(z, f, 2.4022650696e-1f);
    z = fmaf(z, f, 6.9314718056e-1f);
    z = fmaf(z, f, 1.0f);
    float sc = __int_as_float(((int)r + 127) << 23);
    return z * sc;
}

// ---------------- double-buffered tf32 GEMM: BM=128, BN=128, warp tile 64x32 ----
#define GSTR 36
#define ASZ (128 * GSTR)
#define BSZ (128 * GSTR)
#define GEMM_SMEM ((2*ASZ + 2*BSZ) * 4)

template<bool RESID, bool RELU>
__global__ void __launch_bounds__(256)
gemm_db_kernel(const float* __restrict__ A,
               const float* __restrict__ W,
               const float* __restrict__ bias,
               float* __restrict__ C,
               int M, int N, int K)
{
    extern __shared__ float smem[];
    float* Abuf = smem;
    float* Bbuf = smem + 2*ASZ;

    int tid  = threadIdx.x;
    int warp = tid >> 5, lane = tid & 31;
    int g  = lane >> 2, tg = lane & 3;
    int lr = lane & 7, sel = lane >> 3;
    int wm = (warp >> 2) * 64;          // 2 warp-rows
    int wn = (warp & 3)  * 32;          // 4 warp-cols
    int bm = blockIdx.y * 128, bn = blockIdx.x * 128;

    // ldmatrix per-lane row/col offsets
    int a_r = ((sel & 1) << 3) + lr;    // A: rows 0-7 / 8-15 per 16-block
    int a_c = (sel >> 1) << 2;          //    col quads 0-3 / 4-7
    int b_r = ((sel >> 1) << 3) + lr;   // B: nj rows
    int b_c = (sel & 1) << 2;

    auto load_tiles = [&](int k0, int buf) {
        float* As = Abuf + buf * ASZ;
        float* Bs = Bbuf + buf * BSZ;
        #pragma unroll
        for (int it = 0; it < 4; ++it) {
            int idx = tid + it * 256;          // 1024 float4 slots
            int r = idx >> 3, c4 = (idx & 7) << 2;
            cp_async16(&As[r * GSTR + c4], A + (size_t)(bm + r) * K + k0 + c4);
        }
        #pragma unroll
        for (int it = 0; it < 4; ++it) {
            int idx = tid + it * 256;
            int r = idx >> 3, c4 = (idx & 7) << 2;
            cp_async16(&Bs[r * GSTR + c4], W + (size_t)(bn + r) * K + k0 + c4);
        }
    };

    float acc[4][4][4] = {};
    int niter = K >> 5;

    load_tiles(0, 0);
    CP_COMMIT();

    for (int it = 0; it < niter; ++it) {
        if (it + 1 < niter) {
            load_tiles((it + 1) << 5, (it + 1) & 1);
            CP_COMMIT();
            asm volatile("cp.async.wait_group 1;");
        } else {
            asm volatile("cp.async.wait_group 0;");
        }
        __syncthreads();

        float* As = Abuf + (it & 1) * ASZ;
        float* Bs = Bbuf + (it & 1) * BSZ;
        #pragma unroll
        for (int ks = 0; ks < 4; ++ks) {
            int kk = ks * 8;
            uint32_t a[4][4], b[2][4];
            #pragma unroll
            for (int mi = 0; mi < 4; ++mi)
                ldsm_x4(a[mi], &As[(wm + mi*16 + a_r) * GSTR + kk + a_c]);
            ldsm_x4(b[0], &Bs[(wn +      b_r) * GSTR + kk + b_c]);
            ldsm_x4(b[1], &Bs[(wn + 16 + b_r) * GSTR + kk + b_c]);
            #pragma unroll
            for (int mi = 0; mi < 4; ++mi)
                #pragma unroll
                for (int nj = 0; nj < 4; ++nj)
                    mma_tf32(acc[mi][nj], a[mi], &b[nj >> 1][(nj & 1) << 1]);
        }
        __syncthreads();
    }

    #pragma unroll
    for (int mi = 0; mi < 4; ++mi) {
        #pragma unroll
        for (int nj = 0; nj < 4; ++nj) {
            int r0 = bm + wm + mi * 16 + g;
            int c0 = bn + wn + nj * 8 + 2 * tg;
            float bv0 = bias[c0], bv1 = bias[c0 + 1];
            float v00 = acc[mi][nj][0] + bv0;
            float v01 = acc[mi][nj][1] + bv1;
            float v10 = acc[mi][nj][2] + bv0;
            float v11 = acc[mi][nj][3] + bv1;
            if (RELU) {
                v00 = fmaxf(v00, 0.f); v01 = fmaxf(v01, 0.f);
                v10 = fmaxf(v10, 0.f); v11 = fmaxf(v11, 0.f);
            }
            float2* p0 = (float2*)(C + (size_t)r0 * N + c0);
            float2* p1 = (float2*)(C + (size_t)(r0 + 8) * N + c0);
            if (RESID) {
                float2 o0 = *p0, o1 = *p1;
                v00 += o0.x; v01 += o0.y; v10 += o1.x; v11 += o1.y;
            }
            *p0 = make_float2(v00, v01);
            *p1 = make_float2(v10, v11);
        }
    }
}

// ---------------- tensor-core flash attention with ldmatrix ----------------
#define AKS 36
#define VSTR 516
#define APS 68
#define ATTN_SMEM ((T_*AKS + HD_*VSTR + 16*16*APS) * 4)

__global__ void attn_tc_kernel(const float* __restrict__ qkv,
                               float* __restrict__ attn_out)
{
    extern __shared__ float sm[];
    float* Ksh = sm;
    float* Vt  = Ksh + T_*AKS;
    float* Psh = Vt + HD_*VSTR;

    int bh = blockIdx.x, b = bh >> 3, h = bh & 7;
    int tid = threadIdx.x;
    int warp = tid >> 5, lane = tid & 31;
    int g = lane >> 2, tg = lane & 3;
    int lr = lane & 7, sel = lane >> 3;

    const float* base = qkv + (size_t)b * T_ * 768 + h * HD_;
    for (int idx = tid; idx < T_*HD_; idx += 512) {
        int j = idx >> 5, d = idx & 31;
        Ksh[j*AKS + d]  = base[(size_t)j*768 + 256 + d];
        Vt [d*VSTR + j] = base[(size_t)j*768 + 512 + d];
    }
    __syncthreads();

    float* Pw = Psh + warp * 16 * APS;
    const float scale = 0.17677669529663687f;

    int p_r = ((sel & 1) << 3) + lr;
    int p_c = (sel >> 1) << 2;
    int kv_c = sel << 2;

    #pragma unroll
    for (int s = 0; s < 2; ++s) {
        int qt = s ? (31 - warp) : warp;
        int row0 = qt * 16;

        uint32_t aq[4][4];
        const float* q0 = qkv + (size_t)(b*T_ + row0) * 768 + h * HD_;
        #pragma unroll
        for (int ks = 0; ks < 4; ++ks) {
            int kk = ks * 8;
            aq[ks][0] = __float_as_uint(q0[(size_t)g*768     + kk+tg  ] * scale);
            aq[ks][1] = __float_as_uint(q0[(size_t)(g+8)*768 + kk+tg  ] * scale);
            aq[ks][2] = __float_as_uint(q0[(size_t)g*768     + kk+tg+4] * scale);
            aq[ks][3] = __float_as_uint(q0[(size_t)(g+8)*768 + kk+tg+4] * scale);
        }

        int kend  = row0 + 16;
        int jmax0 = kend - 8;
        float m0 = -1e30f, m1 = -1e30f, l0 = 0.f, l1 = 0.f;
        float acc[4][4] = {};

        for (int jb = 0; jb < kend; jb += 64) {
            int chunk = min(64, kend - jb);
            int nbl = chunk >> 3;

            float sc[8][4];
            #pragma unroll
            for (int nb = 0; nb < 8; ++nb) if (nb < nbl) {
                float c4[4] = {0.f, 0.f, 0.f, 0.f};
                const float* krow = &Ksh[(jb + nb*8 + lr) * AKS];
                uint32_t kf[8];
                ldsm_x4(kf,     krow + kv_c);
                ldsm_x4(kf + 4, krow + 16 + kv_c);
                #pragma unroll
                for (int ks = 0; ks < 4; ++ks)
                    mma_tf32(c4, aq[ks], kf + ks*2);
                sc[nb][0] = c4[0]; sc[nb][1] = c4[1];
                sc[nb][2] = c4[2]; sc[nb][3] = c4[3];
            }

            if (jb + chunk > jmax0) {
                #pragma unroll
                for (int nb = 0; nb < 8; ++nb) if (nb < nbl) {
                    int jj = jb + nb*8 + 2*tg;
                    if (jj     >= jmax0) sc[nb][0] = -1e30f;
                    if (jj + 1 >= jmax0) sc[nb][1] = -1e30f;
                }
            }

            float c0 = -1e30f, c1 = -1e30f;
            #pragma unroll
            for (int nb = 0; nb < 8; ++nb) if (nb < nbl) {
                c0 = fmaxf(c0, fmaxf(sc[nb][0], sc[nb][1]));
                c1 = fmaxf(c1, fmaxf(sc[nb][2], sc[nb][3]));
            }
            c0 = fmaxf(c0, __shfl_xor_sync(0xffffffffu, c0, 1));
            c0 = fmaxf(c0, __shfl_xor_sync(0xffffffffu, c0, 2));
            c1 = fmaxf(c1, __shfl_xor_sync(0xffffffffu, c1, 1));
            c1 = fmaxf(c1, __shfl_xor_sync(0xffffffffu, c1, 2));

            float m0n = fmaxf(m0, c0), m1n = fmaxf(m1, c1);
            float f0 = fast_exp(m0 - m0n), f1 = fast_exp(m1 - m1n);

            float sum0 = 0.f, sum1 = 0.f;
            #pragma unroll
            for (int nb = 0; nb < 8; ++nb) if (nb < nbl) {
                float p00 = fast_exp(sc[nb][0] - m0n);
                float p01 = fast_exp(sc[nb][1] - m0n);
                float p10 = fast_exp(sc[nb][2] - m1n);
                float p11 = fast_exp(sc[nb][3] - m1n);
                sum0 += p00 + p01;
                sum1 += p10 + p11;
                *(float2*)(&Pw[(g    )*APS + nb*8 + 2*tg]) = make_float2(p00, p01);
                *(float2*)(&Pw[(g + 8)*APS + nb*8 + 2*tg]) = make_float2(p10, p11);
            }
            sum0 += __shfl_xor_sync(0xffffffffu, sum0, 1);
            sum0 += __shfl_xor_sync(0xffffffffu, sum0, 2);
            sum1 += __shfl_xor_sync(0xffffffffu, sum1, 1);
            sum1 += __shfl_xor_sync(0xffffffffu, sum1, 2);

            l0 = l0 * f0 + sum0;
            l1 = l1 * f1 + sum1;
            m0 = m0n; m1 = m1n;

            #pragma unroll
            for (int nb2 = 0; nb2 < 4; ++nb2) {
                acc[nb2][0] *= f0; acc[nb2][1] *= f0;
                acc[nb2][2] *= f1; acc[nb2][3] *= f1;
            }
            __syncwarp();

            #pragma unroll
            for (int ksp = 0; ksp < 4; ++ksp) if (ksp < (nbl >> 1)) {
                uint32_t pa[2][4];
                ldsm_x4(pa[0], &Pw[p_r*APS + (2*ksp  )*8 + p_c]);
                ldsm_x4(pa[1], &Pw[p_r*APS + (2*ksp+1)*8 + p_c]);
                #pragma unroll
                for (int nb2 = 0; nb2 < 4; ++nb2) {
                    uint32_t vf[4];
                    ldsm_x4(vf, &Vt[(nb2*8 + lr)*VSTR + jb + ksp*16 + kv_c]);
                    mma_tf32(acc[nb2], pa[0], vf);
                    mma_tf32(acc[nb2], pa[1], vf + 2);
                }
            }
            __syncwarp();
        }

        float inv0 = 1.f / l0, inv1 = 1.f / l1;
        #pragma unroll
        for (int nb2 = 0; nb2 < 4; ++nb2) {
            int d = nb2*8 + 2*tg;
            float* o0 = attn_out + (size_t)(b*T_ + row0 + g    ) * D_ + h*HD_ + d;
            float* o1 = attn_out + (size_t)(b*T_ + row0 + g + 8) * D_ + h*HD_ + d;
            *(float2*)o0 = make_float2(acc[nb2][0]*inv0, acc[nb2][1]*inv0);
            *(float2*)o1 = make_float2(acc[nb2][2]*inv1, acc[nb2][3]*inv1);
        }
    }
}

// ---------------- launch ----------------
extern "C" void kernel_launch(void* const* d_in, const int* in_sizes, int n_in,
                              void* d_out, int out_size)
{
    const float*         latents  = (const float*)d_in[0];
    const int*           move_ids = (const int*)d_in[1];
    const void*          mask     = d_in[2];
    const float*         pos      = (const float*)d_in[3];
    const float*         efrom    = (const float*)d_in[4];
    const float*         eto      = (const float*)d_in[5];
    const float*         epromo   = (const float*)d_in[6];
    const float*         in_proj_w= (const float*)d_in[7];
    const float*         in_proj_b= (const float*)d_in[8];
    const float*         out_w    = (const float*)d_in[9];
    const float*         out_b    = (const float*)d_in[10];
    const float*         fc1_w    = (const float*)d_in[11];
    const float*         fc1_b    = (const float*)d_in[12];
    const float*         fc2_w    = (const float*)d_in[13];
    const float*         fc2_b    = (const float*)d_in[14];
    const float*         norm_w   = (const float*)d_in[15];
    const float*         norm_b   = (const float*)d_in[16];
    float* out = (float*)d_out;

    float *px, *pln, *pqkv, *pattn, *ph1;
    cudaGetSymbolAddress((void**)&px,    g_x);
    cudaGetSymbolAddress((void**)&pln,   g_ln);
    cudaGetSymbolAddress((void**)&pqkv,  g_qkv);
    cudaGetSymbolAddress((void**)&pattn, g_attn);
    cudaGetSymbolAddress((void**)&ph1,   g_h1);

    cudaFuncSetAttribute(attn_tc_kernel,
                         cudaFuncAttributeMaxDynamicSharedMemorySize, ATTN_SMEM);
    cudaFuncSetAttribute(gemm_db_kernel<false,false>,
                         cudaFuncAttributeMaxDynamicSharedMemorySize, GEMM_SMEM);
    cudaFuncSetAttribute(gemm_db_kernel<true,false>,
                         cudaFuncAttributeMaxDynamicSharedMemorySize, GEMM_SMEM);
    cudaFuncSetAttribute(gemm_db_kernel<false,true>,
                         cudaFuncAttributeMaxDynamicSharedMemorySize, GEMM_SMEM);

    detect_mask_kernel<<<1, 256>>>((const unsigned char*)mask);
    embed_kernel<<<M_, 256>>>(latents, move_ids, pos, efrom, eto, epromo);

    for (int l = 0; l < L_; ++l) {
        ln_kernel<<<M_/8, 256>>>(px, norm_w, norm_b, pln);
        gemm_db_kernel<false,false><<<dim3(3*D_/128, M_/128), 256, GEMM_SMEM>>>(
            pln, in_proj_w + (size_t)l*3*D_*D_, in_proj_b + l*3*D_, pqkv, M_, 3*D_, D_);
        attn_tc_kernel<<<B_*H_, 512, ATTN_SMEM>>>(pqkv, pattn);
        gemm_db_kernel<true,false><<<dim3(D_/128, M_/128), 256, GEMM_SMEM>>>(
            pattn, out_w + (size_t)l*D_*D_, out_b + l*D_, px, M_, D_, D_);
        ln_kernel<<<M_/8, 256>>>(px, norm_w, norm_b, pln);
        gemm_db_kernel<false,true><<<dim3(FF_/128, M_/128), 256, GEMM_SMEM>>>(
            pln, fc1_w + (size_t)l*FF_*D_, fc1_b + l*FF_, ph1, M_, FF_, D_);
        gemm_db_kernel<true,false><<<dim3(D_/128, M_/128), 256, GEMM_SMEM>>>(
            ph1, fc2_w + (size_t)l*D_*FF_, fc2_b + l*D_, px, M_, D_, FF_);
    }

    ln_mask_kernel<<<M_/8, 256>>>(px, norm_w, norm_b,
                                  (const unsigned char*)mask, (const int*)mask,
                                  latents, out);
}